// round 4
// baseline (speedup 1.0000x reference)
#include <cuda_runtime.h>
#include <cuda_bf16.h>
#include <math.h>

// Shapes: B=64, N=1024, F=4, H=128. BN = 65536 nodes.
// Output: pi [64,1024] then v [64,1] -> 65600 floats.
#define BN 65536
#define H 128
#define NTILES 1024    // node tiles of 64
#define GRID_LOGITS 296

typedef unsigned long long ull;

__device__ float g_hx[H];

__device__ __forceinline__ float tanh_fast(float x) {
    float r;
    asm("tanh.approx.f32 %0, %1;" : "=f"(r) : "f"(x));
    return r;
}
__device__ __forceinline__ float to_tf32(float x) {
    float r;
    asm("cvt.rna.tf32.f32 %0, %1;" : "=f"(r) : "f"(x));
    return r;
}
// ---- packed f32x2 helpers (FFMA2 path ptxas won't auto-emit) ----
__device__ __forceinline__ ull pack2(float lo, float hi) {
    ull r; asm("mov.b64 %0, {%1, %2};" : "=l"(r) : "f"(lo), "f"(hi)); return r;
}
__device__ __forceinline__ void unpack2(ull p, float& lo, float& hi) {
    asm("mov.b64 {%0, %1}, %2;" : "=f"(lo), "=f"(hi) : "l"(p));
}
__device__ __forceinline__ ull fma2(ull a, ull b, ull c) {
    ull r; asm("fma.rn.f32x2 %0, %1, %2, %3;" : "=l"(r) : "l"(a), "l"(b), "l"(c)); return r;
}
__device__ __forceinline__ ull mul2(ull a, ull b) {
    ull r; asm("mul.rn.f32x2 %0, %1, %2;" : "=l"(r) : "l"(a), "l"(b)); return r;
}
__device__ __forceinline__ ull add2(ull a, ull b) {
    ull r; asm("add.rn.f32x2 %0, %1, %2;" : "=l"(r) : "l"(a), "l"(b)); return r;
}

// ---------------------------------------------------------------------------
// Kernel 0: hx (batch-invariant LSTM state) + v scalar. 1 block, 512 threads.
// ---------------------------------------------------------------------------
__global__ void k_hx(const float* __restrict__ Wih, const float* __restrict__ bih,
                     const float* __restrict__ bhh, const float* __restrict__ q,
                     const float* __restrict__ Wval, const float* __restrict__ bval,
                     float* __restrict__ out) {
    __shared__ float qs[128];
    __shared__ float gs[512];
    __shared__ float vred[128];
    int t = threadIdx.x;
    if (t < 128) qs[t] = q[t];
    __syncthreads();
    const float4* w4 = (const float4*)Wih + t * 32;
    const float4* q4 = (const float4*)qs;
    float4 a4 = make_float4(0.f, 0.f, 0.f, 0.f);
    #pragma unroll
    for (int i = 0; i < 32; i++) {
        float4 w = w4[i];
        float4 qq = q4[i];
        a4.x += w.x * qq.x; a4.y += w.y * qq.y;
        a4.z += w.z * qq.z; a4.w += w.w * qq.w;
    }
    gs[t] = a4.x + a4.y + a4.z + a4.w + bih[t] + bhh[t];
    __syncthreads();
    if (t < 128) {
        float ig = gs[t];
        float gg = gs[256 + t];
        float og = gs[384 + t];
        float si = 1.f / (1.f + __expf(-ig));
        float so = 1.f / (1.f + __expf(-og));
        float cx = si * tanh_fast(gg);
        float hx = so * tanh_fast(cx);
        g_hx[t] = hx;
        vred[t] = hx * Wval[t];
    }
    __syncthreads();
    for (int s = 64; s > 0; s >>= 1) {
        if (t < s) vred[t] += vred[t + s];
        __syncthreads();
    }
    float v = vred[0] + bval[0];
    if (t < 64) out[BN + t] = v;
}

// ---------------------------------------------------------------------------
// Kernel 1: logits. tf32 mma GEMM + dual-pipe (MUFU + packed-poly) epilogue.
// Persistent-ish: grid=296, each block stages W_attn ONCE, then grid-strides
// over 1024 node-tiles of 64 nodes.
// ---------------------------------------------------------------------------
#define AS_STRIDE 132
#define ES_STRIDE 72
#define AS_WORDS (128 * AS_STRIDE)          // 16896
#define ES_WORDS (128 * ES_STRIDE)          // 9216
#define SM_WORDS (AS_WORDS + ES_WORDS + 512 + 128 + 128 + 128 + 128)

__global__ __launch_bounds__(128, 2)
void k_logits(const float* __restrict__ nf, const float* __restrict__ Wemb,
              const float* __restrict__ bemb, const float* __restrict__ Wattn,
              const float* __restrict__ vparam, float* __restrict__ out) {
    extern __shared__ float sm[];
    float* As  = sm;                         // [128][132]
    float* es  = As + AS_WORDS;              // [128][72]
    float* wes = es + ES_WORDS;              // 512 (W_emb)
    float* bes = wes + 512;                  // 128
    float* hxs = bes + 128;                  // 128
    float* vps = hxs + 128;                  // 128
    float* red = vps + 128;                  // [64][2]

    int t = threadIdx.x;

    // ---- one-time staging: A = tf32(W_attn), vectorized ----
    for (int i = t * 4; i < 16384; i += 512) {
        float4 w = *(const float4*)(Wattn + i);
        int h = i >> 7, k = i & 127;
        float4 v;
        v.x = to_tf32(w.x); v.y = to_tf32(w.y);
        v.z = to_tf32(w.z); v.w = to_tf32(w.w);
        *(float4*)&As[h * AS_STRIDE + k] = v;
    }
    for (int i = t; i < 512; i += 128) wes[i] = Wemb[i];
    if (t < 128) {
        bes[t] = bemb[t];
        hxs[t] = g_hx[t];
        vps[t] = vparam[t];
    }

    int lane = t & 31, w = t >> 5;
    int g = lane >> 2, tc = lane & 3;
    int wm = w >> 1, wn = w & 1;
    int hb = wm * 64;
    int nb = wn * 32;

    // poly coefficients (deg-7 odd Taylor of tanh), packed
    const ull C3 = pack2(-0.3333333333f, -0.3333333333f);
    const ull C5 = pack2(0.1333333333f, 0.1333333333f);
    const ull C7 = pack2(-0.0539682540f, -0.0539682540f);

    for (int tile = blockIdx.x; tile < NTILES; tile += GRID_LOGITS) {
        int base = tile * 64;
        __syncthreads();   // prior tile done with es/red (also covers staging)

        // Embedding: e[k][n] = tf32(relu(b[k] + x[n].W_emb[k])); 2 thr/node.
        {
            int n = t >> 1;
            int half = t & 1;
            float4 x4 = __ldg((const float4*)nf + (base + n));
            int k0 = half * 64;
            #pragma unroll 8
            for (int k = k0; k < k0 + 64; k++) {
                float e = bes[k] + x4.x * wes[k * 4 + 0] + x4.y * wes[k * 4 + 1]
                                 + x4.z * wes[k * 4 + 2] + x4.w * wes[k * 4 + 3];
                es[k * ES_STRIDE + n] = to_tf32(fmaxf(e, 0.f));
            }
        }
        __syncthreads();

        // ---- tensor-core GEMM: C[h][n], warp tile 64x32 ----
        float accr[4][4][4];
        #pragma unroll
        for (int mi = 0; mi < 4; mi++)
            #pragma unroll
            for (int ni = 0; ni < 4; ni++)
                #pragma unroll
                for (int j = 0; j < 4; j++) accr[mi][ni][j] = 0.f;

        #pragma unroll 4
        for (int kt = 0; kt < 16; kt++) {
            int kb = kt * 8;
            float af[4][4];
            #pragma unroll
            for (int mi = 0; mi < 4; mi++) {
                int r0 = (hb + mi * 16 + g) * AS_STRIDE + kb + tc;
                af[mi][0] = As[r0];
                af[mi][1] = As[r0 + 8 * AS_STRIDE];
                af[mi][2] = As[r0 + 4];
                af[mi][3] = As[r0 + 8 * AS_STRIDE + 4];
            }
            float bf[4][2];
            #pragma unroll
            for (int ni = 0; ni < 4; ni++) {
                int c0 = (kb + tc) * ES_STRIDE + nb + ni * 8 + g;
                bf[ni][0] = es[c0];
                bf[ni][1] = es[c0 + 4 * ES_STRIDE];
            }
            #pragma unroll
            for (int mi = 0; mi < 4; mi++)
                #pragma unroll
                for (int ni = 0; ni < 4; ni++) {
                    asm volatile(
                        "mma.sync.aligned.m16n8k8.row.col.f32.tf32.tf32.f32 "
                        "{%0,%1,%2,%3}, {%4,%5,%6,%7}, {%8,%9}, {%0,%1,%2,%3};"
                        : "+f"(accr[mi][ni][0]), "+f"(accr[mi][ni][1]),
                          "+f"(accr[mi][ni][2]), "+f"(accr[mi][ni][3])
                        : "r"(__float_as_uint(af[mi][0])), "r"(__float_as_uint(af[mi][1])),
                          "r"(__float_as_uint(af[mi][2])), "r"(__float_as_uint(af[mi][3])),
                          "r"(__float_as_uint(bf[ni][0])), "r"(__float_as_uint(bf[ni][1])));
                }
        }

        // ---- dual-pipe epilogue: s2[ni] = packed sum over h of v*tanh(y) ----
        // pair lo/hi = columns n, n+1. mi 0,1 -> MUFU path; mi 2,3 -> packed poly.
        ull s2[4];
        #pragma unroll
        for (int ni = 0; ni < 4; ni++) s2[ni] = pack2(0.f, 0.f);

        #pragma unroll
        for (int mi = 0; mi < 4; mi++) {
            int h0 = hb + mi * 16 + g;
            ull hxa = pack2(hxs[h0], hxs[h0]);
            ull hxb = pack2(hxs[h0 + 8], hxs[h0 + 8]);
            ull va  = pack2(vps[h0], vps[h0]);
            ull vb  = pack2(vps[h0 + 8], vps[h0 + 8]);
            #pragma unroll
            for (int ni = 0; ni < 4; ni++) {
                ull pa = pack2(accr[mi][ni][0], accr[mi][ni][1]);
                ull pb = pack2(accr[mi][ni][2], accr[mi][ni][3]);
                ull ya = add2(pa, hxa);
                ull yb = add2(pb, hxb);
                if (mi < 2) {
                    // MUFU path (exact range)
                    float l0, l1;
                    unpack2(ya, l0, l1);
                    ull ta = pack2(tanh_fast(l0), tanh_fast(l1));
                    s2[ni] = fma2(va, ta, s2[ni]);
                    unpack2(yb, l0, l1);
                    ull tb = pack2(tanh_fast(l0), tanh_fast(l1));
                    s2[ni] = fma2(vb, tb, s2[ni]);
                } else {
                    // packed deg-7 odd poly: tanh(y) ~= y*(1 + u*(c3 + c5 u + c7 u^2))
                    ull ua = mul2(ya, ya);
                    ull qa = fma2(ua, C7, C5);
                    qa = fma2(ua, qa, C3);
                    ull wa = mul2(ya, ua);
                    ull ta = fma2(wa, qa, ya);
                    s2[ni] = fma2(va, ta, s2[ni]);

                    ull ub = mul2(yb, yb);
                    ull qb = fma2(ub, C7, C5);
                    qb = fma2(ub, qb, C3);
                    ull wb = mul2(yb, ub);
                    ull tb = fma2(wb, qb, yb);
                    s2[ni] = fma2(vb, tb, s2[ni]);
                }
            }
        }

        float pl[4][2];
        #pragma unroll
        for (int ni = 0; ni < 4; ni++) unpack2(s2[ni], pl[ni][0], pl[ni][1]);

        #pragma unroll
        for (int off = 4; off < 32; off <<= 1)
            #pragma unroll
            for (int ni = 0; ni < 4; ni++)
                #pragma unroll
                for (int j = 0; j < 2; j++)
                    pl[ni][j] += __shfl_xor_sync(0xffffffff, pl[ni][j], off);
        if (g == 0) {
            #pragma unroll
            for (int ni = 0; ni < 4; ni++)
                #pragma unroll
                for (int j = 0; j < 2; j++)
                    red[(nb + ni * 8 + 2 * tc + j) * 2 + wm] = pl[ni][j];
        }
        __syncthreads();
        if (t < 64) out[base + t] = red[t * 2] + red[t * 2 + 1];
    }
}

// ---------------------------------------------------------------------------
// Kernel 2: softmax over N=1024 per batch, in place.
// ---------------------------------------------------------------------------
__global__ void k_softmax(float* __restrict__ out) {
    __shared__ float red[256];
    int b = blockIdx.x;
    int t = threadIdx.x;
    float* row = out + b * 1024;
    float4 x = ((const float4*)row)[t];
    float m = fmaxf(fmaxf(x.x, x.y), fmaxf(x.z, x.w));
    red[t] = m;
    __syncthreads();
    for (int s = 128; s > 0; s >>= 1) {
        if (t < s) red[t] = fmaxf(red[t], red[t + s]);
        __syncthreads();
    }
    float M = red[0];
    __syncthreads();
    float e0 = __expf(x.x - M);
    float e1 = __expf(x.y - M);
    float e2 = __expf(x.z - M);
    float e3 = __expf(x.w - M);
    red[t] = e0 + e1 + e2 + e3;
    __syncthreads();
    for (int s = 128; s > 0; s >>= 1) {
        if (t < s) red[t] += red[t + s];
        __syncthreads();
    }
    float inv = 1.f / red[0];
    float4 r;
    r.x = e0 * inv; r.y = e1 * inv; r.z = e2 * inv; r.w = e3 * inv;
    ((float4*)row)[t] = r;
}

// ---------------------------------------------------------------------------
extern "C" void kernel_launch(void* const* d_in, const int* in_sizes, int n_in,
                              void* d_out, int out_size) {
    const float* nf     = (const float*)d_in[0];
    const float* Wemb   = (const float*)d_in[2];
    const float* bemb   = (const float*)d_in[3];
    const float* Wih    = (const float*)d_in[4];
    const float* bih    = (const float*)d_in[5];
    const float* bhh    = (const float*)d_in[7];
    const float* query  = (const float*)d_in[8];
    const float* Wattn  = (const float*)d_in[9];
    const float* vparam = (const float*)d_in[10];
    const float* Wval   = (const float*)d_in[11];
    const float* bval   = (const float*)d_in[12];
    float* out = (float*)d_out;

    static int smem_set = 0;
    const int smem_bytes = SM_WORDS * 4;
    if (!smem_set) {
        cudaFuncSetAttribute(k_logits, cudaFuncAttributeMaxDynamicSharedMemorySize,
                             smem_bytes);
        smem_set = 1;
    }

    k_hx<<<1, 512>>>(Wih, bih, bhh, query, Wval, bval, out);
    k_logits<<<GRID_LOGITS, 128, smem_bytes>>>(nf, Wemb, bemb, Wattn, vparam, out);
    k_softmax<<<64, 256>>>(out);
}

// round 5
// speedup vs baseline: 1.1730x; 1.1730x over previous
#include <cuda_runtime.h>
#include <cuda_bf16.h>
#include <math.h>

// Shapes: B=64, N=1024, F=4, H=128. BN = 65536 nodes.
// Output: pi [64,1024] then v [64,1] -> 65600 floats.
#define BN 65536
#define H 128
#define NTILES 1024
#define GRID_LOGITS 296

typedef unsigned long long ull;

__device__ float g_hx[H];
__device__ float g_gates[512];

__device__ __forceinline__ float tanh_fast(float x) {
    float r;
    asm("tanh.approx.f32 %0, %1;" : "=f"(r) : "f"(x));
    return r;
}
__device__ __forceinline__ float to_tf32(float x) {
    float r;
    asm("cvt.rna.tf32.f32 %0, %1;" : "=f"(r) : "f"(x));
    return r;
}
// ---- packed f32x2 helpers ----
__device__ __forceinline__ ull pack2(float lo, float hi) {
    ull r; asm("mov.b64 %0, {%1, %2};" : "=l"(r) : "f"(lo), "f"(hi)); return r;
}
__device__ __forceinline__ void unpack2(ull p, float& lo, float& hi) {
    asm("mov.b64 {%0, %1}, %2;" : "=f"(lo), "=f"(hi) : "l"(p));
}
__device__ __forceinline__ ull fma2(ull a, ull b, ull c) {
    ull r; asm("fma.rn.f32x2 %0, %1, %2, %3;" : "=l"(r) : "l"(a), "l"(b), "l"(c)); return r;
}
__device__ __forceinline__ ull mul2(ull a, ull b) {
    ull r; asm("mul.rn.f32x2 %0, %1, %2;" : "=l"(r) : "l"(a), "l"(b)); return r;
}
__device__ __forceinline__ ull add2(ull a, ull b) {
    ull r; asm("add.rn.f32x2 %0, %1, %2;" : "=l"(r) : "l"(a), "l"(b)); return r;
}

// ---------------------------------------------------------------------------
// Kernel 0a: gates = q . W_ih^T + b_ih + b_hh  (512 rows, spread over 32 SMs)
// 32 blocks x 128 threads; 16 rows/block, 8 threads/row, 16 elems each.
// ---------------------------------------------------------------------------
__global__ void k_gates(const float* __restrict__ Wih, const float* __restrict__ bih,
                        const float* __restrict__ bhh, const float* __restrict__ q) {
    __shared__ float qs[128];
    int t = threadIdx.x;
    qs[t] = q[t];
    __syncthreads();
    int row = blockIdx.x * 16 + (t >> 3);
    int part = t & 7;
    const float4* w4 = (const float4*)(Wih + row * 128 + part * 16);
    const float4* q4 = (const float4*)(qs + part * 16);
    float s = 0.f;
    #pragma unroll
    for (int i = 0; i < 4; i++) {
        float4 w = w4[i];
        float4 qq = q4[i];
        s += w.x * qq.x + w.y * qq.y + w.z * qq.z + w.w * qq.w;
    }
    s += __shfl_xor_sync(0xffffffff, s, 1);
    s += __shfl_xor_sync(0xffffffff, s, 2);
    s += __shfl_xor_sync(0xffffffff, s, 4);
    if (part == 0) g_gates[row] = s + bih[row] + bhh[row];
}

// ---------------------------------------------------------------------------
// Kernel 0b: hx nonlinearity + v scalar. 1 block, 128 threads.
// ---------------------------------------------------------------------------
__global__ void k_hxv(const float* __restrict__ Wval, const float* __restrict__ bval,
                      float* __restrict__ out) {
    __shared__ float vred[128];
    int t = threadIdx.x;
    float ig = g_gates[t];
    float gg = g_gates[256 + t];
    float og = g_gates[384 + t];
    float si = 1.f / (1.f + __expf(-ig));
    float so = 1.f / (1.f + __expf(-og));
    float cx = si * tanh_fast(gg);
    float hx = so * tanh_fast(cx);
    g_hx[t] = hx;
    vred[t] = hx * Wval[t];
    __syncthreads();
    for (int s = 64; s > 0; s >>= 1) {
        if (t < s) vred[t] += vred[t + s];
        __syncthreads();
    }
    float v = vred[0] + bval[0];
    if (t < 64) out[BN + t] = v;
}

// ---------------------------------------------------------------------------
// Kernel 1: logits. tf32 mma GEMM + dual-pipe epilogue. Persistent blocks.
// As layout: k permuted within each 8-chunk (j<4 -> 2j, else 2j-7) so the
// mma A-pair (k, k+4) is adjacent -> LDS.64. Stride 136: bank = 8g+2tc,
// distinct within each 16-lane phase -> conflict-free.
// ---------------------------------------------------------------------------
#define AS_STRIDE 136
#define ES_STRIDE 72
#define AS_WORDS (128 * AS_STRIDE)          // 17408
#define ES_WORDS (128 * ES_STRIDE)          // 9216
#define SM_WORDS (AS_WORDS + ES_WORDS + 512 + 128 + 128 + 128 + 128)

__global__ __launch_bounds__(128, 2)
void k_logits(const float* __restrict__ nf, const float* __restrict__ Wemb,
              const float* __restrict__ bemb, const float* __restrict__ Wattn,
              const float* __restrict__ vparam, float* __restrict__ out) {
    extern __shared__ float sm[];
    float* As  = sm;                         // [128][136], k-permuted
    float* es  = As + AS_WORDS;              // [128][72]
    float* wes = es + ES_WORDS;              // 512 (W_emb)
    float* bes = wes + 512;                  // 128
    float* hxs = bes + 128;                  // 128
    float* vps = hxs + 128;                  // 128
    float* red = vps + 128;                  // [64][2]

    int t = threadIdx.x;

    // ---- one-time staging: A = tf32(W_attn), k-permuted ----
    for (int i = t * 4; i < 16384; i += 512) {
        float4 w = *(const float4*)(Wattn + i);
        int h = i >> 7, k = i & 127;
        int kb8 = k & ~7;
        int j = k & 7;      // 0 or 4 (i is a multiple of 4)
        // elements j..j+3 map to: j<4 -> 2j,2j+2,2j+4,2j+6 ; j=4 -> 1,3,5,7
        int c0 = (j < 4) ? (kb8 + 2 * j) : (kb8 + 2 * j - 7);
        float* dst = &As[h * AS_STRIDE + c0];
        dst[0] = to_tf32(w.x);
        dst[2] = to_tf32(w.y);
        dst[4] = to_tf32(w.z);
        dst[6] = to_tf32(w.w);
    }
    for (int i = t; i < 512; i += 128) wes[i] = Wemb[i];
    if (t < 128) {
        bes[t] = bemb[t];
        hxs[t] = g_hx[t];
        vps[t] = vparam[t];
    }

    int lane = t & 31, w = t >> 5;
    int g = lane >> 2, tc = lane & 3;
    int wm = w >> 1, wn = w & 1;
    int hb = wm * 64;
    int nb = wn * 32;

    const ull C3 = pack2(-0.3333333333f, -0.3333333333f);
    const ull C5 = pack2(0.1333333333f, 0.1333333333f);
    const ull C7 = pack2(-0.0539682540f, -0.0539682540f);

    for (int tile = blockIdx.x; tile < NTILES; tile += GRID_LOGITS) {
        int base = tile * 64;
        __syncthreads();   // prior tile done with es/red (also covers staging)

        // Embedding: e[k][n] = tf32(relu(b[k] + x[n].W_emb[k])); 2 thr/node.
        {
            int n = t >> 1;
            int half = t & 1;
            float4 x4 = __ldg((const float4*)nf + (base + n));
            int k0 = half * 64;
            #pragma unroll 8
            for (int k = k0; k < k0 + 64; k++) {
                float4 we = *(const float4*)&wes[k * 4];
                float e = bes[k] + x4.x * we.x + x4.y * we.y
                                 + x4.z * we.z + x4.w * we.w;
                es[k * ES_STRIDE + n] = to_tf32(fmaxf(e, 0.f));
            }
        }
        __syncthreads();

        // ---- tensor-core GEMM: C[h][n], warp tile 64x32 ----
        float accr[4][4][4];
        #pragma unroll
        for (int mi = 0; mi < 4; mi++)
            #pragma unroll
            for (int ni = 0; ni < 4; ni++)
                #pragma unroll
                for (int j = 0; j < 4; j++) accr[mi][ni][j] = 0.f;

        #pragma unroll 4
        for (int kt = 0; kt < 16; kt++) {
            int kb = kt * 8;
            float af[4][4];
            #pragma unroll
            for (int mi = 0; mi < 4; mi++) {
                int r0 = (hb + mi * 16 + g) * AS_STRIDE + kb + 2 * tc;
                float2 lo = *(const float2*)&As[r0];                    // k, k+4
                float2 hi = *(const float2*)&As[r0 + 8 * AS_STRIDE];
                af[mi][0] = lo.x; af[mi][2] = lo.y;
                af[mi][1] = hi.x; af[mi][3] = hi.y;
            }
            float bf[4][2];
            #pragma unroll
            for (int ni = 0; ni < 4; ni++) {
                int c0 = (kb + tc) * ES_STRIDE + nb + ni * 8 + g;
                bf[ni][0] = es[c0];
                bf[ni][1] = es[c0 + 4 * ES_STRIDE];
            }
            #pragma unroll
            for (int mi = 0; mi < 4; mi++)
                #pragma unroll
                for (int ni = 0; ni < 4; ni++) {
                    asm volatile(
                        "mma.sync.aligned.m16n8k8.row.col.f32.tf32.tf32.f32 "
                        "{%0,%1,%2,%3}, {%4,%5,%6,%7}, {%8,%9}, {%0,%1,%2,%3};"
                        : "+f"(accr[mi][ni][0]), "+f"(accr[mi][ni][1]),
                          "+f"(accr[mi][ni][2]), "+f"(accr[mi][ni][3])
                        : "r"(__float_as_uint(af[mi][0])), "r"(__float_as_uint(af[mi][1])),
                          "r"(__float_as_uint(af[mi][2])), "r"(__float_as_uint(af[mi][3])),
                          "r"(__float_as_uint(bf[ni][0])), "r"(__float_as_uint(bf[ni][1])));
                }
        }

        // ---- dual-pipe epilogue ----
        ull s2[4];
        #pragma unroll
        for (int ni = 0; ni < 4; ni++) s2[ni] = pack2(0.f, 0.f);

        #pragma unroll
        for (int mi = 0; mi < 4; mi++) {
            int h0 = hb + mi * 16 + g;
            ull hxa = pack2(hxs[h0], hxs[h0]);
            ull hxb = pack2(hxs[h0 + 8], hxs[h0 + 8]);
            ull va  = pack2(vps[h0], vps[h0]);
            ull vb  = pack2(vps[h0 + 8], vps[h0 + 8]);
            #pragma unroll
            for (int ni = 0; ni < 4; ni++) {
                ull pa = pack2(accr[mi][ni][0], accr[mi][ni][1]);
                ull pb = pack2(accr[mi][ni][2], accr[mi][ni][3]);
                ull ya = add2(pa, hxa);
                ull yb = add2(pb, hxb);
                if (mi < 2) {
                    float l0, l1;
                    unpack2(ya, l0, l1);
                    ull ta = pack2(tanh_fast(l0), tanh_fast(l1));
                    s2[ni] = fma2(va, ta, s2[ni]);
                    unpack2(yb, l0, l1);
                    ull tb = pack2(tanh_fast(l0), tanh_fast(l1));
                    s2[ni] = fma2(vb, tb, s2[ni]);
                } else {
                    ull ua = mul2(ya, ya);
                    ull qa = fma2(ua, C7, C5);
                    qa = fma2(ua, qa, C3);
                    ull wa = mul2(ya, ua);
                    ull ta = fma2(wa, qa, ya);
                    s2[ni] = fma2(va, ta, s2[ni]);

                    ull ub = mul2(yb, yb);
                    ull qb = fma2(ub, C7, C5);
                    qb = fma2(ub, qb, C3);
                    ull wb = mul2(yb, ub);
                    ull tb = fma2(wb, qb, yb);
                    s2[ni] = fma2(vb, tb, s2[ni]);
                }
            }
        }

        float pl[4][2];
        #pragma unroll
        for (int ni = 0; ni < 4; ni++) unpack2(s2[ni], pl[ni][0], pl[ni][1]);

        #pragma unroll
        for (int off = 4; off < 32; off <<= 1)
            #pragma unroll
            for (int ni = 0; ni < 4; ni++)
                #pragma unroll
                for (int j = 0; j < 2; j++)
                    pl[ni][j] += __shfl_xor_sync(0xffffffff, pl[ni][j], off);
        if (g == 0) {
            #pragma unroll
            for (int ni = 0; ni < 4; ni++)
                #pragma unroll
                for (int j = 0; j < 2; j++)
                    red[(nb + ni * 8 + 2 * tc + j) * 2 + wm] = pl[ni][j];
        }
        __syncthreads();
        if (t < 64) out[base + t] = red[t * 2] + red[t * 2 + 1];
    }
}

// ---------------------------------------------------------------------------
// Kernel 2: softmax over N=1024 per batch, in place.
// ---------------------------------------------------------------------------
__global__ void k_softmax(float* __restrict__ out) {
    __shared__ float red[256];
    int b = blockIdx.x;
    int t = threadIdx.x;
    float* row = out + b * 1024;
    float4 x = ((const float4*)row)[t];
    float m = fmaxf(fmaxf(x.x, x.y), fmaxf(x.z, x.w));
    red[t] = m;
    __syncthreads();
    for (int s = 128; s > 0; s >>= 1) {
        if (t < s) red[t] = fmaxf(red[t], red[t + s]);
        __syncthreads();
    }
    float M = red[0];
    __syncthreads();
    float e0 = __expf(x.x - M);
    float e1 = __expf(x.y - M);
    float e2 = __expf(x.z - M);
    float e3 = __expf(x.w - M);
    red[t] = e0 + e1 + e2 + e3;
    __syncthreads();
    for (int s = 128; s > 0; s >>= 1) {
        if (t < s) red[t] += red[t + s];
        __syncthreads();
    }
    float inv = 1.f / red[0];
    float4 r;
    r.x = e0 * inv; r.y = e1 * inv; r.z = e2 * inv; r.w = e3 * inv;
    ((float4*)row)[t] = r;
}

// ---------------------------------------------------------------------------
extern "C" void kernel_launch(void* const* d_in, const int* in_sizes, int n_in,
                              void* d_out, int out_size) {
    const float* nf     = (const float*)d_in[0];
    const float* Wemb   = (const float*)d_in[2];
    const float* bemb   = (const float*)d_in[3];
    const float* Wih    = (const float*)d_in[4];
    const float* bih    = (const float*)d_in[5];
    const float* bhh    = (const float*)d_in[7];
    const float* query  = (const float*)d_in[8];
    const float* Wattn  = (const float*)d_in[9];
    const float* vparam = (const float*)d_in[10];
    const float* Wval   = (const float*)d_in[11];
    const float* bval   = (const float*)d_in[12];
    float* out = (float*)d_out;

    static int smem_set = 0;
    const int smem_bytes = SM_WORDS * 4;
    if (!smem_set) {
        cudaFuncSetAttribute(k_logits, cudaFuncAttributeMaxDynamicSharedMemorySize,
                             smem_bytes);
        smem_set = 1;
    }

    k_gates<<<32, 128>>>(Wih, bih, bhh, query);
    k_hxv<<<1, 128>>>(Wval, bval, out);
    k_logits<<<GRID_LOGITS, 128, smem_bytes>>>(nf, Wemb, bemb, Wattn, vparam, out);
    k_softmax<<<64, 256>>>(out);
}

// round 7
// speedup vs baseline: 1.5129x; 1.2897x over previous
#include <cuda_runtime.h>
#include <cuda_fp16.h>
#include <math.h>
#include <cstdint>

// Shapes: B=64, N=1024, F=4, H=128. BN = 65536 nodes.
// Output: pi [64,1024] then v [64,1] -> 65600 floats.
#define BN 65536
#define NTILES 1024
#define GRID_LOGITS 296

typedef unsigned long long ull;

__device__ float g_hx[128];
__device__ float g_gates[512];

// ---------------- scalar helpers ----------------
__device__ __forceinline__ float tanh_fast(float x) {
    float r; asm("tanh.approx.f32 %0, %1;" : "=f"(r) : "f"(x)); return r;
}
// ---------------- packed f32x2 helpers ----------------
__device__ __forceinline__ ull pack2(float lo, float hi) {
    ull r; asm("mov.b64 %0, {%1, %2};" : "=l"(r) : "f"(lo), "f"(hi)); return r;
}
__device__ __forceinline__ void unpack2(ull p, float& lo, float& hi) {
    asm("mov.b64 {%0, %1}, %2;" : "=f"(lo), "=f"(hi) : "l"(p));
}
__device__ __forceinline__ ull fma2(ull a, ull b, ull c) {
    ull r; asm("fma.rn.f32x2 %0, %1, %2, %3;" : "=l"(r) : "l"(a), "l"(b), "l"(c)); return r;
}
__device__ __forceinline__ ull mul2(ull a, ull b) {
    ull r; asm("mul.rn.f32x2 %0, %1, %2;" : "=l"(r) : "l"(a), "l"(b)); return r;
}
__device__ __forceinline__ ull add2(ull a, ull b) {
    ull r; asm("add.rn.f32x2 %0, %1, %2;" : "=l"(r) : "l"(a), "l"(b)); return r;
}

// ---------------------------------------------------------------------------
// Kernel 0a: gates = q . W_ih^T + b_ih + b_hh  (512 rows over 32 blocks)
// ---------------------------------------------------------------------------
__global__ void k_gates(const float* __restrict__ Wih, const float* __restrict__ bih,
                        const float* __restrict__ bhh, const float* __restrict__ q) {
    __shared__ float qs[128];
    int t = threadIdx.x;
    qs[t] = q[t];
    __syncthreads();
    int row = blockIdx.x * 16 + (t >> 3);
    int part = t & 7;
    const float4* w4 = (const float4*)(Wih + row * 128 + part * 16);
    const float4* q4 = (const float4*)(qs + part * 16);
    float s = 0.f;
    #pragma unroll
    for (int i = 0; i < 4; i++) {
        float4 w = w4[i];
        float4 qq = q4[i];
        s += w.x * qq.x + w.y * qq.y + w.z * qq.z + w.w * qq.w;
    }
    s += __shfl_xor_sync(0xffffffff, s, 1);
    s += __shfl_xor_sync(0xffffffff, s, 2);
    s += __shfl_xor_sync(0xffffffff, s, 4);
    if (part == 0) g_gates[row] = s + bih[row] + bhh[row];
}

// ---------------------------------------------------------------------------
// Kernel 0b: hx nonlinearity + v scalar. 1 block, 128 threads.
// ---------------------------------------------------------------------------
__global__ void k_hxv(const float* __restrict__ Wval, const float* __restrict__ bval,
                      float* __restrict__ out) {
    __shared__ float vred[128];
    int t = threadIdx.x;
    float ig = g_gates[t];
    float gg = g_gates[256 + t];
    float og = g_gates[384 + t];
    float si = 1.f / (1.f + __expf(-ig));
    float so = 1.f / (1.f + __expf(-og));
    float cx = si * tanh_fast(gg);
    float hx = so * tanh_fast(cx);
    g_hx[t] = hx;
    vred[t] = hx * Wval[t];
    __syncthreads();
    for (int s = 64; s > 0; s >>= 1) {
        if (t < s) vred[t] += vred[t + s];
        __syncthreads();
    }
    float v = vred[0] + bval[0];
    if (t < 64) out[BN + t] = v;
}

// ---------------------------------------------------------------------------
// Kernel 1: logits via fp16 mma.sync m16n8k16, fp32 accum.
//   A = W_attn [128h x 128k] half2 (k-pairs), SW-free padded layout, staged once.
//   B = relu-embedding [64n x 128k] half2, rebuilt per tile.
// half2 k-pair columns permuted within each octet so that the fragment pair
// (k2, k2+4) is adjacent -> LDS.64. Stride 72 half2 -> bank = 8g+2tc,
// conflict-free per 16-lane phase.
// ---------------------------------------------------------------------------
#define AH_STRIDE 72
#define AS_OFF   0        // 128*72 half2 = 9216 floats
#define ES_OFF   9216     // 64*72 half2 = 4608 floats
#define XS_OFF   13824    // 256 floats
#define HXS_OFF  14080    // 128
#define VPS_OFF  14208    // 128
#define RED_OFF  14336    // 128
#define SM_FLOATS 14464

__global__ __launch_bounds__(128, 2)
void k_logits(const float* __restrict__ nf, const float* __restrict__ Wemb,
              const float* __restrict__ bemb, const float* __restrict__ Wattn,
              const float* __restrict__ vparam, float* __restrict__ out) {
    extern __shared__ float sm[];
    __half2* as2 = (__half2*)sm;              // [128][72]
    __half2* es2 = (__half2*)(sm + ES_OFF);   // [64][72]
    float4* xs   = (float4*)(sm + XS_OFF);
    float* hxs   = sm + HXS_OFF;
    float* vps   = sm + VPS_OFF;
    float* red   = sm + RED_OFF;

    int t = threadIdx.x;
    int lane = t & 31, w = t >> 5;
    int g = lane >> 2, tc = lane & 3;
    int wm = w >> 1, wn = w & 1;
    int hb = wm * 64, nb_w = wn * 32;

    // ---- one-time staging: A = half2(W_attn), permuted k-pair columns ----
    for (int i = t * 4; i < 16384; i += 512) {
        float4 wv = *(const float4*)(Wattn + i);
        int h = i >> 7, k = i & 127;
        int k2 = k >> 1;                 // multiple of 2
        int kb8 = k2 & ~7, j = k2 & 7;   // j in {0,2,4,6}
        int c1 = kb8 + ((j < 4) ? 2 * j : 2 * j - 7);
        as2[h * AH_STRIDE + c1]     = __floats2half2_rn(wv.x, wv.y);
        as2[h * AH_STRIDE + c1 + 2] = __floats2half2_rn(wv.z, wv.w);
    }
    hxs[t] = g_hx[t];
    vps[t] = vparam[t];

    // ---- per-thread embedding weights: k2 quartet K0..K0+3, node octet ----
    int K0 = (t >> 3) * 4;
    int nodeb = (t & 7) * 8;
    ull w2[16], b2[4];
    int cols[4];
    #pragma unroll
    for (int kp = 0; kp < 4; kp++) {
        int k2v = K0 + kp;
        int kk = 2 * k2v;
        #pragma unroll
        for (int f = 0; f < 4; f++)
            w2[kp * 4 + f] = pack2(Wemb[kk * 4 + f], Wemb[(kk + 1) * 4 + f]);
        b2[kp] = pack2(bemb[kk], bemb[kk + 1]);
        int j = k2v & 7;
        cols[kp] = (k2v & ~7) + ((j < 4) ? 2 * j : 2 * j - 7);
    }

    const ull C3 = pack2(-0.3333333333f, -0.3333333333f);
    const ull C5 = pack2(0.1333333333f, 0.1333333333f);
    const ull C7 = pack2(-0.0539682540f, -0.0539682540f);
    const __half2 hzero = __floats2half2_rn(0.f, 0.f);

    for (int tile = blockIdx.x; tile < NTILES; tile += GRID_LOGITS) {
        int base = tile * 64;
        __syncthreads();   // es/red free from previous tile
        if (t < 64) xs[t] = __ldg((const float4*)nf + (base + t));
        __syncthreads();

        // ---- embedding: es2[n][col(kp)] = half2(relu(e_even), relu(e_odd)) ----
        #pragma unroll
        for (int nn = 0; nn < 8; nn++) {
            int n = nodeb + ((nn + (t >> 3)) & 7);
            float4 x = xs[n];
            ull x0 = pack2(x.x, x.x), x1 = pack2(x.y, x.y);
            ull x2 = pack2(x.z, x.z), x3 = pack2(x.w, x.w);
            __half2* dst = es2 + n * AH_STRIDE;
            #pragma unroll
            for (int kp = 0; kp < 4; kp++) {
                ull e = b2[kp];
                e = fma2(x0, w2[kp * 4 + 0], e);
                e = fma2(x1, w2[kp * 4 + 1], e);
                e = fma2(x2, w2[kp * 4 + 2], e);
                e = fma2(x3, w2[kp * 4 + 3], e);
                float lo, hi;
                unpack2(e, lo, hi);
                __half2 hv = __hmax2(__floats2half2_rn(lo, hi), hzero);
                dst[cols[kp]] = hv;
            }
        }
        __syncthreads();

        // ---- fp16 tensor GEMM: C[h][n], warp tile 64x32, K chunks of 16 ----
        float accr[4][4][4];
        #pragma unroll
        for (int mi = 0; mi < 4; mi++)
            #pragma unroll
            for (int ni = 0; ni < 4; ni++)
                #pragma unroll
                for (int j = 0; j < 4; j++) accr[mi][ni][j] = 0.f;

        #pragma unroll
        for (int kt = 0; kt < 8; kt++) {
            int cb = kt * 8 + 2 * tc;
            uint2 alo[4], ahi[4];
            #pragma unroll
            for (int mi = 0; mi < 4; mi++) {
                int r = hb + mi * 16 + g;
                alo[mi] = *(const uint2*)(as2 + r * AH_STRIDE + cb);        // a0,a2
                ahi[mi] = *(const uint2*)(as2 + (r + 8) * AH_STRIDE + cb);  // a1,a3
            }
            uint2 bfr[4];
            #pragma unroll
            for (int ni = 0; ni < 4; ni++) {
                int n = nb_w + ni * 8 + g;
                bfr[ni] = *(const uint2*)(es2 + n * AH_STRIDE + cb);        // b0,b1
            }
            #pragma unroll
            for (int mi = 0; mi < 4; mi++)
                #pragma unroll
                for (int ni = 0; ni < 4; ni++) {
                    asm volatile(
                        "mma.sync.aligned.m16n8k16.row.col.f32.f16.f16.f32 "
                        "{%0,%1,%2,%3}, {%4,%5,%6,%7}, {%8,%9}, {%0,%1,%2,%3};"
                        : "+f"(accr[mi][ni][0]), "+f"(accr[mi][ni][1]),
                          "+f"(accr[mi][ni][2]), "+f"(accr[mi][ni][3])
                        : "r"(alo[mi].x), "r"(ahi[mi].x),
                          "r"(alo[mi].y), "r"(ahi[mi].y),
                          "r"(bfr[ni].x), "r"(bfr[ni].y));
                }
        }

        // ---- dual-pipe epilogue (MUFU + packed poly), reduce over h ----
        ull s2[4];
        #pragma unroll
        for (int ni = 0; ni < 4; ni++) s2[ni] = pack2(0.f, 0.f);

        #pragma unroll
        for (int mi = 0; mi < 4; mi++) {
            int h0 = hb + mi * 16 + g;
            ull hxa = pack2(hxs[h0], hxs[h0]);
            ull hxb = pack2(hxs[h0 + 8], hxs[h0 + 8]);
            ull va  = pack2(vps[h0], vps[h0]);
            ull vb  = pack2(vps[h0 + 8], vps[h0 + 8]);
            #pragma unroll
            for (int ni = 0; ni < 4; ni++) {
                ull pa = pack2(accr[mi][ni][0], accr[mi][ni][1]);
                ull pb = pack2(accr[mi][ni][2], accr[mi][ni][3]);
                ull ya = add2(pa, hxa);
                ull yb = add2(pb, hxb);
                if (mi < 2) {
                    float l0, l1;
                    unpack2(ya, l0, l1);
                    ull ta = pack2(tanh_fast(l0), tanh_fast(l1));
                    s2[ni] = fma2(va, ta, s2[ni]);
                    unpack2(yb, l0, l1);
                    ull tb = pack2(tanh_fast(l0), tanh_fast(l1));
                    s2[ni] = fma2(vb, tb, s2[ni]);
                } else {
                    ull ua = mul2(ya, ya);
                    ull qa = fma2(ua, C7, C5);
                    qa = fma2(ua, qa, C3);
                    ull wa = mul2(ya, ua);
                    ull ta = fma2(wa, qa, ya);
                    s2[ni] = fma2(va, ta, s2[ni]);

                    ull ub = mul2(yb, yb);
                    ull qb = fma2(ub, C7, C5);
                    qb = fma2(ub, qb, C3);
                    ull wb = mul2(yb, ub);
                    ull tb = fma2(wb, qb, yb);
                    s2[ni] = fma2(vb, tb, s2[ni]);
                }
            }
        }

        float pl[4][2];
        #pragma unroll
        for (int ni = 0; ni < 4; ni++) unpack2(s2[ni], pl[ni][0], pl[ni][1]);

        #pragma unroll
        for (int off = 4; off < 32; off <<= 1)
            #pragma unroll
            for (int ni = 0; ni < 4; ni++)
                #pragma unroll
                for (int j = 0; j < 2; j++)
                    pl[ni][j] += __shfl_xor_sync(0xffffffff, pl[ni][j], off);
        if (g == 0) {
            #pragma unroll
            for (int ni = 0; ni < 4; ni++)
                #pragma unroll
                for (int j = 0; j < 2; j++)
                    red[(nb_w + ni * 8 + 2 * tc + j) * 2 + wm] = pl[ni][j];
        }
        __syncthreads();
        if (t < 64) out[base + t] = red[t * 2] + red[t * 2 + 1];
    }
}

// ---------------------------------------------------------------------------
// Kernel 2: softmax over N=1024 per batch, in place.
// ---------------------------------------------------------------------------
__global__ void k_softmax(float* __restrict__ out) {
    __shared__ float red[256];
    int b = blockIdx.x;
    int t = threadIdx.x;
    float* row = out + b * 1024;
    float4 x = ((const float4*)row)[t];
    float m = fmaxf(fmaxf(x.x, x.y), fmaxf(x.z, x.w));
    red[t] = m;
    __syncthreads();
    for (int s = 128; s > 0; s >>= 1) {
        if (t < s) red[t] = fmaxf(red[t], red[t + s]);
        __syncthreads();
    }
    float M = red[0];
    __syncthreads();
    float e0 = __expf(x.x - M);
    float e1 = __expf(x.y - M);
    float e2 = __expf(x.z - M);
    float e3 = __expf(x.w - M);
    red[t] = e0 + e1 + e2 + e3;
    __syncthreads();
    for (int s = 128; s > 0; s >>= 1) {
        if (t < s) red[t] += red[t + s];
        __syncthreads();
    }
    float inv = 1.f / red[0];
    float4 r;
    r.x = e0 * inv; r.y = e1 * inv; r.z = e2 * inv; r.w = e3 * inv;
    ((float4*)row)[t] = r;
}

// ---------------------------------------------------------------------------
extern "C" void kernel_launch(void* const* d_in, const int* in_sizes, int n_in,
                              void* d_out, int out_size) {
    const float* nf     = (const float*)d_in[0];
    const float* Wemb   = (const float*)d_in[2];
    const float* bemb   = (const float*)d_in[3];
    const float* Wih    = (const float*)d_in[4];
    const float* bih    = (const float*)d_in[5];
    const float* bhh    = (const float*)d_in[7];
    const float* query  = (const float*)d_in[8];
    const float* Wattn  = (const float*)d_in[9];
    const float* vparam = (const float*)d_in[10];
    const float* Wval   = (const float*)d_in[11];
    const float* bval   = (const float*)d_in[12];
    float* out = (float*)d_out;

    static int smem_set = 0;
    const int smem_bytes = SM_FLOATS * 4;
    if (!smem_set) {
        cudaFuncSetAttribute(k_logits, cudaFuncAttributeMaxDynamicSharedMemorySize,
                             smem_bytes);
        smem_set = 1;
    }

    k_gates<<<32, 128>>>(Wih, bih, bhh, query);
    k_hxv<<<1, 128>>>(Wval, bval, out);
    k_logits<<<GRID_LOGITS, 128, smem_bytes>>>(nf, Wemb, bemb, Wattn, vparam, out);
    k_softmax<<<64, 256>>>(out);
}